// round 6
// baseline (speedup 1.0000x reference)
#include <cuda_runtime.h>
#include <math.h>

#define NN 30000
#define EE 300000
#define RR 3
#define KIN 256
#define F1 128   // HEADS*HID
#define F2 256   // HEADS*OUT

// ---------------- scratch (device globals; no allocation allowed) ----------
__device__ __align__(16) float g_z1[(size_t)RR * NN * F1];   // 46 MB
__device__ __align__(16) float g_z2[(size_t)RR * NN * F2];   // 92 MB
__device__ __align__(16) float g_h[(size_t)NN * F1];         // 15 MB
__device__ __align__(16) float g_el1[RR * NN * 4];
__device__ __align__(16) float g_er1[RR * NN * 4];
__device__ __align__(16) float g_el2[RR * NN * 4];
__device__ __align__(16) float g_er2[RR * NN * 4];
__device__ int g_deg[RR * NN];
__device__ int g_cur[RR * NN];
__device__ int g_rowoff[RR * (NN + 1)];
__device__ int g_col[RR * EE];

__device__ __forceinline__ float lrelu(float x) { return x > 0.f ? x : 0.2f * x; }

__device__ __forceinline__ unsigned f2tf32(float v) {
    unsigned u;
    asm("cvt.rna.tf32.f32 %0, %1;" : "=r"(u) : "f"(v));
    return u;
}

// ---------------- CSR build --------------------------------------------------
__global__ void k_zero() {
    int i = blockIdx.x * blockDim.x + threadIdx.x;
    if (i < RR * NN) { g_deg[i] = 0; g_cur[i] = 0; }
}

__global__ void k_hist(const int* __restrict__ dst) {
    int i = blockIdx.x * blockDim.x + threadIdx.x;
    if (i < RR * EE) {
        int r = i / EE;
        atomicAdd(&g_deg[r * NN + dst[i]], 1);
    }
}

__global__ void k_scan() {
    int r = blockIdx.x;
    __shared__ int sh[1024];
    __shared__ int carry;
    int t = threadIdx.x;
    if (t == 0) { carry = 0; g_rowoff[r * (NN + 1)] = 0; }
    __syncthreads();
    for (int base = 0; base < NN; base += 1024) {
        int i = base + t;
        int v = (i < NN) ? g_deg[r * NN + i] : 0;
        sh[t] = v;
        __syncthreads();
        for (int off = 1; off < 1024; off <<= 1) {
            int x = (t >= off) ? sh[t - off] : 0;
            __syncthreads();
            sh[t] += x;
            __syncthreads();
        }
        if (i < NN) g_rowoff[r * (NN + 1) + i + 1] = carry + sh[t];
        __syncthreads();
        if (t == 0) carry += sh[1023];
        __syncthreads();
    }
}

__global__ void k_scatter(const int* __restrict__ src, const int* __restrict__ dst) {
    int i = blockIdx.x * blockDim.x + threadIdx.x;
    if (i < RR * EE) {
        int r = i / EE;
        int d = dst[i];
        int pos = atomicAdd(&g_cur[r * NN + d], 1);
        g_col[(size_t)r * EE + g_rowoff[r * (NN + 1) + d] + pos] = src[i];
    }
}

// ---------------- TF32 tensor-core GEMM: C[r] = A @ B[r] ---------------------
#define SSTR 132

__global__ __launch_bounds__(256, 2)
void k_sgemm_tf32(const float* __restrict__ Aext, const float* __restrict__ Bg,
                  int M, int K, int Nc, int layer) {
    const float* A = (layer == 1) ? Aext : g_h;
    float* C = (layer == 1) ? g_z1 : g_z2;
    int r = blockIdx.z;
    const float* B = Bg + (size_t)r * K * Nc;
    C += (size_t)r * M * Nc;

    __shared__ unsigned As[2][16 * SSTR];   // [k][m]
    __shared__ unsigned Bs[2][16 * SSTR];   // [k][n]

    int tid = threadIdx.x;
    int lane = tid & 31;
    int wid = tid >> 5;
    int wm = (wid & 1) * 64;
    int wn = (wid >> 1) * 32;
    int gid = lane >> 2;
    int tig = lane & 3;

    int row0 = blockIdx.y * 128, col0 = blockIdx.x * 128;

    int am = tid >> 2;
    int ak = (tid & 3) * 4;
    int bk = tid >> 4;
    int bn = (tid & 15) * 4;

    float acc[4][4][4];
#pragma unroll
    for (int i = 0; i < 4; i++)
#pragma unroll
        for (int j = 0; j < 4; j++)
#pragma unroll
            for (int q = 0; q < 4; q++) acc[i][j][q] = 0.f;

    int nstage = K >> 4;

    {
        float4 va0, va1, vb0, vb1;
        int gr0 = row0 + am, gr1 = row0 + am + 64;
        va0 = (gr0 < M) ? *reinterpret_cast<const float4*>(&A[(size_t)gr0 * K + ak])
                        : make_float4(0, 0, 0, 0);
        va1 = (gr1 < M) ? *reinterpret_cast<const float4*>(&A[(size_t)gr1 * K + ak])
                        : make_float4(0, 0, 0, 0);
        vb0 = *reinterpret_cast<const float4*>(&B[(size_t)bk * Nc + col0 + bn]);
        vb1 = *reinterpret_cast<const float4*>(&B[(size_t)bk * Nc + col0 + 64 + bn]);
        As[0][(ak + 0) * SSTR + am] = f2tf32(va0.x);
        As[0][(ak + 1) * SSTR + am] = f2tf32(va0.y);
        As[0][(ak + 2) * SSTR + am] = f2tf32(va0.z);
        As[0][(ak + 3) * SSTR + am] = f2tf32(va0.w);
        As[0][(ak + 0) * SSTR + am + 64] = f2tf32(va1.x);
        As[0][(ak + 1) * SSTR + am + 64] = f2tf32(va1.y);
        As[0][(ak + 2) * SSTR + am + 64] = f2tf32(va1.z);
        As[0][(ak + 3) * SSTR + am + 64] = f2tf32(va1.w);
        Bs[0][bk * SSTR + bn + 0] = f2tf32(vb0.x);
        Bs[0][bk * SSTR + bn + 1] = f2tf32(vb0.y);
        Bs[0][bk * SSTR + bn + 2] = f2tf32(vb0.z);
        Bs[0][bk * SSTR + bn + 3] = f2tf32(vb0.w);
        Bs[0][bk * SSTR + 64 + bn + 0] = f2tf32(vb1.x);
        Bs[0][bk * SSTR + 64 + bn + 1] = f2tf32(vb1.y);
        Bs[0][bk * SSTR + 64 + bn + 2] = f2tf32(vb1.z);
        Bs[0][bk * SSTR + 64 + bn + 3] = f2tf32(vb1.w);
    }
    __syncthreads();

    int buf = 0;
    for (int s = 0; s < nstage; s++) {
        float4 va0, va1, vb0, vb1;
        bool more = (s + 1) < nstage;
        if (more) {
            int k0 = (s + 1) << 4;
            int gr0 = row0 + am, gr1 = row0 + am + 64;
            va0 = (gr0 < M) ? *reinterpret_cast<const float4*>(&A[(size_t)gr0 * K + k0 + ak])
                            : make_float4(0, 0, 0, 0);
            va1 = (gr1 < M) ? *reinterpret_cast<const float4*>(&A[(size_t)gr1 * K + k0 + ak])
                            : make_float4(0, 0, 0, 0);
            vb0 = *reinterpret_cast<const float4*>(&B[(size_t)(k0 + bk) * Nc + col0 + bn]);
            vb1 = *reinterpret_cast<const float4*>(&B[(size_t)(k0 + bk) * Nc + col0 + 64 + bn]);
        }

        const unsigned* as = As[buf];
        const unsigned* bs = Bs[buf];
#pragma unroll
        for (int kk = 0; kk < 16; kk += 8) {
            unsigned a[4][4], b[4][2];
#pragma unroll
            for (int i = 0; i < 4; i++) {
                int m = wm + i * 16 + gid;
                a[i][0] = as[(kk + tig) * SSTR + m];
                a[i][1] = as[(kk + tig) * SSTR + m + 8];
                a[i][2] = as[(kk + tig + 4) * SSTR + m];
                a[i][3] = as[(kk + tig + 4) * SSTR + m + 8];
            }
#pragma unroll
            for (int j = 0; j < 4; j++) {
                int n = wn + j * 8 + gid;
                b[j][0] = bs[(kk + tig) * SSTR + n];
                b[j][1] = bs[(kk + tig + 4) * SSTR + n];
            }
#pragma unroll
            for (int i = 0; i < 4; i++)
#pragma unroll
                for (int j = 0; j < 4; j++) {
                    asm volatile(
                        "mma.sync.aligned.m16n8k8.row.col.f32.tf32.tf32.f32 "
                        "{%0,%1,%2,%3}, {%4,%5,%6,%7}, {%8,%9}, {%0,%1,%2,%3};\n"
                        : "+f"(acc[i][j][0]), "+f"(acc[i][j][1]),
                          "+f"(acc[i][j][2]), "+f"(acc[i][j][3])
                        : "r"(a[i][0]), "r"(a[i][1]), "r"(a[i][2]), "r"(a[i][3]),
                          "r"(b[j][0]), "r"(b[j][1]));
                }
        }

        if (more) {
            unsigned* asn = As[buf ^ 1];
            unsigned* bsn = Bs[buf ^ 1];
            asn[(ak + 0) * SSTR + am] = f2tf32(va0.x);
            asn[(ak + 1) * SSTR + am] = f2tf32(va0.y);
            asn[(ak + 2) * SSTR + am] = f2tf32(va0.z);
            asn[(ak + 3) * SSTR + am] = f2tf32(va0.w);
            asn[(ak + 0) * SSTR + am + 64] = f2tf32(va1.x);
            asn[(ak + 1) * SSTR + am + 64] = f2tf32(va1.y);
            asn[(ak + 2) * SSTR + am + 64] = f2tf32(va1.z);
            asn[(ak + 3) * SSTR + am + 64] = f2tf32(va1.w);
            bsn[bk * SSTR + bn + 0] = f2tf32(vb0.x);
            bsn[bk * SSTR + bn + 1] = f2tf32(vb0.y);
            bsn[bk * SSTR + bn + 2] = f2tf32(vb0.z);
            bsn[bk * SSTR + bn + 3] = f2tf32(vb0.w);
            bsn[bk * SSTR + 64 + bn + 0] = f2tf32(vb1.x);
            bsn[bk * SSTR + 64 + bn + 1] = f2tf32(vb1.y);
            bsn[bk * SSTR + 64 + bn + 2] = f2tf32(vb1.z);
            bsn[bk * SSTR + 64 + bn + 3] = f2tf32(vb1.w);
        }
        __syncthreads();
        buf ^= 1;
    }

#pragma unroll
    for (int i = 0; i < 4; i++) {
#pragma unroll
        for (int j = 0; j < 4; j++) {
            int gr = row0 + wm + i * 16 + gid;
            int gc = col0 + wn + j * 8 + 2 * tig;
            if (gr < M)
                *reinterpret_cast<float2*>(&C[(size_t)gr * Nc + gc]) =
                    make_float2(acc[i][j][0], acc[i][j][1]);
            if (gr + 8 < M)
                *reinterpret_cast<float2*>(&C[(size_t)(gr + 8) * Nc + gc]) =
                    make_float2(acc[i][j][2], acc[i][j][3]);
        }
    }
}

// ---------------- attention projections: warp per (node, relation) -----------
__global__ void k_attn1(const float* __restrict__ al, const float* __restrict__ ar) {
    int gw = (blockIdx.x * blockDim.x + threadIdx.x) >> 5;
    if (gw >= NN * RR) return;
    int r = gw / NN, n = gw - r * NN;
    int lane = threadIdx.x & 31;
    float4 z = *reinterpret_cast<const float4*>(&g_z1[((size_t)(r * NN + n)) * F1 + lane * 4]);
    float4 a4 = *reinterpret_cast<const float4*>(&al[r * F1 + lane * 4]);
    float4 r4 = *reinterpret_cast<const float4*>(&ar[r * F1 + lane * 4]);
    float pl = z.x * a4.x + z.y * a4.y + z.z * a4.z + z.w * a4.w;
    float pr = z.x * r4.x + z.y * r4.y + z.z * r4.z + z.w * r4.w;
#pragma unroll
    for (int o = 4; o > 0; o >>= 1) {   // reduce within 8-lane head group
        pl += __shfl_xor_sync(0xffffffffu, pl, o);
        pr += __shfl_xor_sync(0xffffffffu, pr, o);
    }
    if ((lane & 7) == 0) {
        int h = lane >> 3;
        g_el1[(r * NN + n) * 4 + h] = pl;
        g_er1[(r * NN + n) * 4 + h] = pr;
    }
}

__global__ void k_attn2(const float* __restrict__ al, const float* __restrict__ ar) {
    int gw = (blockIdx.x * blockDim.x + threadIdx.x) >> 5;
    if (gw >= NN * RR) return;
    int r = gw / NN, n = gw - r * NN;
    int lane = threadIdx.x & 31;
    const float* zp = &g_z2[((size_t)(r * NN + n)) * F2 + lane * 8];
    const float* ap = &al[r * F2 + lane * 8];
    const float* rp = &ar[r * F2 + lane * 8];
    float4 z0 = *reinterpret_cast<const float4*>(zp);
    float4 z1 = *reinterpret_cast<const float4*>(zp + 4);
    float4 a0 = *reinterpret_cast<const float4*>(ap);
    float4 a1 = *reinterpret_cast<const float4*>(ap + 4);
    float4 r0 = *reinterpret_cast<const float4*>(rp);
    float4 r1 = *reinterpret_cast<const float4*>(rp + 4);
    float pl = z0.x * a0.x + z0.y * a0.y + z0.z * a0.z + z0.w * a0.w
             + z1.x * a1.x + z1.y * a1.y + z1.z * a1.z + z1.w * a1.w;
    float pr = z0.x * r0.x + z0.y * r0.y + z0.z * r0.z + z0.w * r0.w
             + z1.x * r1.x + z1.y * r1.y + z1.z * r1.z + z1.w * r1.w;
#pragma unroll
    for (int o = 4; o > 0; o >>= 1) {
        pl += __shfl_xor_sync(0xffffffffu, pl, o);
        pr += __shfl_xor_sync(0xffffffffu, pr, o);
    }
    if ((lane & 7) == 0) {
        int h = lane >> 3;
        g_el2[(r * NN + n) * 4 + h] = pl;
        g_er2[(r * NN + n) * 4 + h] = pr;
    }
}

// ------- layer-1 agg: 2 warps per dst node, each handles 2 heads (64 cols) ---
__global__ __launch_bounds__(256)
void k_agg1(const float* __restrict__ b1) {
    int gw = (blockIdx.x * blockDim.x + threadIdx.x) >> 5;
    if (gw >= 2 * NN) return;
    int n = gw >> 1;
    int p = gw & 1;              // head pair: heads 2p, 2p+1
    int lane = threadIdx.x & 31;
    int cbase = p * 64;          // column base in g_h / g_z1

    float t0 = 0.f, t1 = 0.f;    // cols cbase+lane, cbase+32+lane
#pragma unroll
    for (int r = 0; r < RR; r++) {
        int beg = g_rowoff[r * (NN + 1) + n];
        int end = g_rowoff[r * (NN + 1) + n + 1];
        if (beg == end) continue;
        float2 erd = *reinterpret_cast<const float2*>(&g_er1[(r * NN + n) * 4 + 2 * p]);
        float d0 = 0.f, d1 = 0.f, a0 = 0.f, a1 = 0.f;
        const int* colp = &g_col[(size_t)r * EE];
        for (int i = beg; i < end; i++) {
            int s = colp[i];
            float2 el = *reinterpret_cast<const float2*>(&g_el1[(r * NN + s) * 4 + 2 * p]);
            float w0 = __expf(lrelu(el.x + erd.x));
            float w1 = __expf(lrelu(el.y + erd.y));
            d0 += w0; d1 += w1;
            const float* z = &g_z1[((size_t)(r * NN + s)) * F1 + cbase];
            a0 += w0 * z[lane];
            a1 += w1 * z[32 + lane];
        }
        t0 += a0 / d0; t1 += a1 / d1;
    }
    t0 += b1[cbase + lane]      + b1[F1 + cbase + lane]      + b1[2 * F1 + cbase + lane];
    t1 += b1[cbase + 32 + lane] + b1[F1 + cbase + 32 + lane] + b1[2 * F1 + cbase + 32 + lane];
    size_t o = (size_t)n * F1 + cbase;
    g_h[o + lane]      = fmaxf(t0, 0.f);
    g_h[o + 32 + lane] = fmaxf(t1, 0.f);
}

// ------- layer-2 agg: 2 warps per dst node (2 heads each) + head-mean --------
__global__ __launch_bounds__(256)
void k_agg2(const float* __restrict__ b2, float* __restrict__ out) {
    int gw = (blockIdx.x * blockDim.x + threadIdx.x) >> 5;
    int lane = threadIdx.x & 31;
    int wib = (threadIdx.x >> 5);          // warp in block (0..7)
    __shared__ float part[8][64];
    bool active = (gw < 2 * NN);
    int n = gw >> 1;
    int p = gw & 1;                        // heads 2p, 2p+1
    float s0 = 0.f, s1 = 0.f;              // partial out[lane], out[32+lane]
    if (active) {
        int cbase = p * 128;               // z2 cols for heads 2p..2p+1
        float tA0 = 0, tA1 = 0, tB0 = 0, tB1 = 0;   // head 2p: out cols lane/32+lane; head 2p+1 ditto
#pragma unroll
        for (int r = 0; r < RR; r++) {
            int beg = g_rowoff[r * (NN + 1) + n];
            int end = g_rowoff[r * (NN + 1) + n + 1];
            if (beg == end) continue;
            float2 erd = *reinterpret_cast<const float2*>(&g_er2[(r * NN + n) * 4 + 2 * p]);
            float d0 = 0.f, d1 = 0.f;
            float a00 = 0.f, a01 = 0.f, a10 = 0.f, a11 = 0.f;
            const int* colp = &g_col[(size_t)r * EE];
            for (int i = beg; i < end; i++) {
                int s = colp[i];
                float2 el = *reinterpret_cast<const float2*>(&g_el2[(r * NN + s) * 4 + 2 * p]);
                float w0 = __expf(lrelu(el.x + erd.x));
                float w1 = __expf(lrelu(el.y + erd.y));
                d0 += w0; d1 += w1;
                const float* z = &g_z2[((size_t)(r * NN + s)) * F2 + cbase];
                a00 += w0 * z[lane];       a01 += w0 * z[32 + lane];
                a10 += w1 * z[64 + lane];  a11 += w1 * z[96 + lane];
            }
            tA0 += a00 / d0; tA1 += a01 / d0;
            tB0 += a10 / d1; tB1 += a11 / d1;
        }
        // biases for this warp's two heads (summed over relations)
        int h0 = cbase;          // head 2p cols [cbase, cbase+64)
        int h1 = cbase + 64;     // head 2p+1
        tA0 += b2[h0 + lane]      + b2[F2 + h0 + lane]      + b2[2 * F2 + h0 + lane];
        tA1 += b2[h0 + 32 + lane] + b2[F2 + h0 + 32 + lane] + b2[2 * F2 + h0 + 32 + lane];
        tB0 += b2[h1 + lane]      + b2[F2 + h1 + lane]      + b2[2 * F2 + h1 + lane];
        tB1 += b2[h1 + 32 + lane] + b2[F2 + h1 + 32 + lane] + b2[2 * F2 + h1 + 32 + lane];
        s0 = tA0 + tB0;
        s1 = tA1 + tB1;
    }
    part[wib][lane] = s0;
    part[wib][32 + lane] = s1;
    __syncthreads();
    if (active && p == 0) {
        // combine this node's two warps (wib, wib+1) and write 64 outputs
        float o0 = 0.25f * (part[wib][lane] + part[wib + 1][lane]);
        float o1 = 0.25f * (part[wib][32 + lane] + part[wib + 1][32 + lane]);
        out[(size_t)n * 64 + lane] = o0;
        out[(size_t)n * 64 + 32 + lane] = o1;
    }
}

// ---------------- launch (single stream — overlap experiment reverted) -------
extern "C" void kernel_launch(void* const* d_in, const int* in_sizes, int n_in,
                              void* d_out, int out_size) {
    const float* x   = (const float*)d_in[0];
    const int*   src = (const int*)d_in[1];
    const int*   dst = (const int*)d_in[2];
    const float* W1  = (const float*)d_in[3];
    const float* al1 = (const float*)d_in[4];
    const float* ar1 = (const float*)d_in[5];
    const float* b1  = (const float*)d_in[6];
    const float* W2  = (const float*)d_in[7];
    const float* al2 = (const float*)d_in[8];
    const float* ar2 = (const float*)d_in[9];
    const float* b2  = (const float*)d_in[10];
    float* out = (float*)d_out;

    // CSR by dst, per relation
    k_zero<<<(RR * NN + 255) / 256, 256>>>();
    k_hist<<<(RR * EE + 255) / 256, 256>>>(dst);
    k_scan<<<RR, 1024>>>();
    k_scatter<<<(RR * EE + 255) / 256, 256>>>(src, dst);

    // layer 1
    dim3 g1(F1 / 128, (NN + 127) / 128, RR);
    k_sgemm_tf32<<<g1, 256>>>(x, W1, NN, KIN, F1, 1);
    k_attn1<<<(NN * RR + 7) / 8, 256>>>(al1, ar1);
    k_agg1<<<(2 * NN + 7) / 8, 256>>>(b1);

    // layer 2
    dim3 g2(F2 / 128, (NN + 127) / 128, RR);
    k_sgemm_tf32<<<g2, 256>>>(nullptr, W2, NN, F1, F2, 2);
    k_attn2<<<(NN * RR + 7) / 8, 256>>>(al2, ar2);
    k_agg2<<<(2 * NN + 7) / 8, 256>>>(b2, out);
}

// round 8
// speedup vs baseline: 1.5987x; 1.5987x over previous
#include <cuda_runtime.h>
#include <math.h>

#define NN 30000
#define EE 300000
#define RR 3
#define KIN 256
#define F1 128   // HEADS*HID
#define F2 256   // HEADS*OUT

// ---------------- scratch (device globals; no allocation allowed) ----------
__device__ __align__(16) float g_z1[(size_t)RR * NN * F1];   // 46 MB
__device__ __align__(16) float g_z2[(size_t)RR * NN * F2];   // 92 MB
__device__ __align__(16) float g_h[(size_t)NN * F1];         // 15 MB
__device__ __align__(16) float g_el1[RR * NN * 4];
__device__ __align__(16) float g_er1[RR * NN * 4];
__device__ __align__(16) float g_el2[RR * NN * 4];
__device__ __align__(16) float g_er2[RR * NN * 4];
__device__ int g_deg[RR * NN];
__device__ int g_cur[RR * NN];
__device__ int g_rowoff[RR * (NN + 1)];
__device__ int g_col[RR * EE];

__device__ __forceinline__ float lrelu(float x) { return x > 0.f ? x : 0.2f * x; }

__device__ __forceinline__ unsigned f2tf32(float v) {
    unsigned u;
    asm("cvt.rna.tf32.f32 %0, %1;" : "=r"(u) : "f"(v));
    return u;
}

// ---------------- CSR build --------------------------------------------------
__global__ void k_zero() {
    int i = blockIdx.x * blockDim.x + threadIdx.x;
    if (i < RR * NN) { g_deg[i] = 0; g_cur[i] = 0; }
}

__global__ void k_hist(const int* __restrict__ dst) {
    int i = blockIdx.x * blockDim.x + threadIdx.x;
    if (i < RR * EE) {
        int r = i / EE;
        atomicAdd(&g_deg[r * NN + dst[i]], 1);
    }
}

__global__ void k_scan() {
    int r = blockIdx.x;
    __shared__ int sh[1024];
    __shared__ int carry;
    int t = threadIdx.x;
    if (t == 0) { carry = 0; g_rowoff[r * (NN + 1)] = 0; }
    __syncthreads();
    for (int base = 0; base < NN; base += 1024) {
        int i = base + t;
        int v = (i < NN) ? g_deg[r * NN + i] : 0;
        sh[t] = v;
        __syncthreads();
        for (int off = 1; off < 1024; off <<= 1) {
            int x = (t >= off) ? sh[t - off] : 0;
            __syncthreads();
            sh[t] += x;
            __syncthreads();
        }
        if (i < NN) g_rowoff[r * (NN + 1) + i + 1] = carry + sh[t];
        __syncthreads();
        if (t == 0) carry += sh[1023];
        __syncthreads();
    }
}

__global__ void k_scatter(const int* __restrict__ src, const int* __restrict__ dst) {
    int i = blockIdx.x * blockDim.x + threadIdx.x;
    if (i < RR * EE) {
        int r = i / EE;
        int d = dst[i];
        int pos = atomicAdd(&g_cur[r * NN + d], 1);
        g_col[(size_t)r * EE + g_rowoff[r * (NN + 1) + d] + pos] = src[i];
    }
}

// ---------------- TF32 tensor-core GEMM: C[r] = A @ B[r] ---------------------
#define SSTR 132

__global__ __launch_bounds__(256, 2)
void k_sgemm_tf32(const float* __restrict__ Aext, const float* __restrict__ Bg,
                  int M, int K, int Nc, int layer) {
    const float* A = (layer == 1) ? Aext : g_h;
    float* C = (layer == 1) ? g_z1 : g_z2;
    int r = blockIdx.z;
    const float* B = Bg + (size_t)r * K * Nc;
    C += (size_t)r * M * Nc;

    __shared__ unsigned As[2][16 * SSTR];   // [k][m]
    __shared__ unsigned Bs[2][16 * SSTR];   // [k][n]

    int tid = threadIdx.x;
    int lane = tid & 31;
    int wid = tid >> 5;
    int wm = (wid & 1) * 64;
    int wn = (wid >> 1) * 32;
    int gid = lane >> 2;
    int tig = lane & 3;

    int row0 = blockIdx.y * 128, col0 = blockIdx.x * 128;

    int am = tid >> 2;
    int ak = (tid & 3) * 4;
    int bk = tid >> 4;
    int bn = (tid & 15) * 4;

    float acc[4][4][4];
#pragma unroll
    for (int i = 0; i < 4; i++)
#pragma unroll
        for (int j = 0; j < 4; j++)
#pragma unroll
            for (int q = 0; q < 4; q++) acc[i][j][q] = 0.f;

    int nstage = K >> 4;

    {
        float4 va0, va1, vb0, vb1;
        int gr0 = row0 + am, gr1 = row0 + am + 64;
        va0 = (gr0 < M) ? *reinterpret_cast<const float4*>(&A[(size_t)gr0 * K + ak])
                        : make_float4(0, 0, 0, 0);
        va1 = (gr1 < M) ? *reinterpret_cast<const float4*>(&A[(size_t)gr1 * K + ak])
                        : make_float4(0, 0, 0, 0);
        vb0 = *reinterpret_cast<const float4*>(&B[(size_t)bk * Nc + col0 + bn]);
        vb1 = *reinterpret_cast<const float4*>(&B[(size_t)bk * Nc + col0 + 64 + bn]);
        As[0][(ak + 0) * SSTR + am] = f2tf32(va0.x);
        As[0][(ak + 1) * SSTR + am] = f2tf32(va0.y);
        As[0][(ak + 2) * SSTR + am] = f2tf32(va0.z);
        As[0][(ak + 3) * SSTR + am] = f2tf32(va0.w);
        As[0][(ak + 0) * SSTR + am + 64] = f2tf32(va1.x);
        As[0][(ak + 1) * SSTR + am + 64] = f2tf32(va1.y);
        As[0][(ak + 2) * SSTR + am + 64] = f2tf32(va1.z);
        As[0][(ak + 3) * SSTR + am + 64] = f2tf32(va1.w);
        Bs[0][bk * SSTR + bn + 0] = f2tf32(vb0.x);
        Bs[0][bk * SSTR + bn + 1] = f2tf32(vb0.y);
        Bs[0][bk * SSTR + bn + 2] = f2tf32(vb0.z);
        Bs[0][bk * SSTR + bn + 3] = f2tf32(vb0.w);
        Bs[0][bk * SSTR + 64 + bn + 0] = f2tf32(vb1.x);
        Bs[0][bk * SSTR + 64 + bn + 1] = f2tf32(vb1.y);
        Bs[0][bk * SSTR + 64 + bn + 2] = f2tf32(vb1.z);
        Bs[0][bk * SSTR + 64 + bn + 3] = f2tf32(vb1.w);
    }
    __syncthreads();

    int buf = 0;
    for (int s = 0; s < nstage; s++) {
        float4 va0, va1, vb0, vb1;
        bool more = (s + 1) < nstage;
        if (more) {
            int k0 = (s + 1) << 4;
            int gr0 = row0 + am, gr1 = row0 + am + 64;
            va0 = (gr0 < M) ? *reinterpret_cast<const float4*>(&A[(size_t)gr0 * K + k0 + ak])
                            : make_float4(0, 0, 0, 0);
            va1 = (gr1 < M) ? *reinterpret_cast<const float4*>(&A[(size_t)gr1 * K + k0 + ak])
                            : make_float4(0, 0, 0, 0);
            vb0 = *reinterpret_cast<const float4*>(&B[(size_t)(k0 + bk) * Nc + col0 + bn]);
            vb1 = *reinterpret_cast<const float4*>(&B[(size_t)(k0 + bk) * Nc + col0 + 64 + bn]);
        }

        const unsigned* as = As[buf];
        const unsigned* bs = Bs[buf];
#pragma unroll
        for (int kk = 0; kk < 16; kk += 8) {
            unsigned a[4][4], b[4][2];
#pragma unroll
            for (int i = 0; i < 4; i++) {
                int m = wm + i * 16 + gid;
                a[i][0] = as[(kk + tig) * SSTR + m];
                a[i][1] = as[(kk + tig) * SSTR + m + 8];
                a[i][2] = as[(kk + tig + 4) * SSTR + m];
                a[i][3] = as[(kk + tig + 4) * SSTR + m + 8];
            }
#pragma unroll
            for (int j = 0; j < 4; j++) {
                int n = wn + j * 8 + gid;
                b[j][0] = bs[(kk + tig) * SSTR + n];
                b[j][1] = bs[(kk + tig + 4) * SSTR + n];
            }
#pragma unroll
            for (int i = 0; i < 4; i++)
#pragma unroll
                for (int j = 0; j < 4; j++) {
                    asm volatile(
                        "mma.sync.aligned.m16n8k8.row.col.f32.tf32.tf32.f32 "
                        "{%0,%1,%2,%3}, {%4,%5,%6,%7}, {%8,%9}, {%0,%1,%2,%3};\n"
                        : "+f"(acc[i][j][0]), "+f"(acc[i][j][1]),
                          "+f"(acc[i][j][2]), "+f"(acc[i][j][3])
                        : "r"(a[i][0]), "r"(a[i][1]), "r"(a[i][2]), "r"(a[i][3]),
                          "r"(b[j][0]), "r"(b[j][1]));
                }
        }

        if (more) {
            unsigned* asn = As[buf ^ 1];
            unsigned* bsn = Bs[buf ^ 1];
            asn[(ak + 0) * SSTR + am] = f2tf32(va0.x);
            asn[(ak + 1) * SSTR + am] = f2tf32(va0.y);
            asn[(ak + 2) * SSTR + am] = f2tf32(va0.z);
            asn[(ak + 3) * SSTR + am] = f2tf32(va0.w);
            asn[(ak + 0) * SSTR + am + 64] = f2tf32(va1.x);
            asn[(ak + 1) * SSTR + am + 64] = f2tf32(va1.y);
            asn[(ak + 2) * SSTR + am + 64] = f2tf32(va1.z);
            asn[(ak + 3) * SSTR + am + 64] = f2tf32(va1.w);
            bsn[bk * SSTR + bn + 0] = f2tf32(vb0.x);
            bsn[bk * SSTR + bn + 1] = f2tf32(vb0.y);
            bsn[bk * SSTR + bn + 2] = f2tf32(vb0.z);
            bsn[bk * SSTR + bn + 3] = f2tf32(vb0.w);
            bsn[bk * SSTR + 64 + bn + 0] = f2tf32(vb1.x);
            bsn[bk * SSTR + 64 + bn + 1] = f2tf32(vb1.y);
            bsn[bk * SSTR + 64 + bn + 2] = f2tf32(vb1.z);
            bsn[bk * SSTR + 64 + bn + 3] = f2tf32(vb1.w);
        }
        __syncthreads();
        buf ^= 1;
    }

#pragma unroll
    for (int i = 0; i < 4; i++) {
#pragma unroll
        for (int j = 0; j < 4; j++) {
            int gr = row0 + wm + i * 16 + gid;
            int gc = col0 + wn + j * 8 + 2 * tig;
            if (gr < M)
                *reinterpret_cast<float2*>(&C[(size_t)gr * Nc + gc]) =
                    make_float2(acc[i][j][0], acc[i][j][1]);
            if (gr + 8 < M)
                *reinterpret_cast<float2*>(&C[(size_t)(gr + 8) * Nc + gc]) =
                    make_float2(acc[i][j][2], acc[i][j][3]);
        }
    }
}

// ---------------- attention projections: warp per (node, relation) -----------
__global__ void k_attn1(const float* __restrict__ al, const float* __restrict__ ar) {
    int gw = (blockIdx.x * blockDim.x + threadIdx.x) >> 5;
    if (gw >= NN * RR) return;
    int r = gw / NN, n = gw - r * NN;
    int lane = threadIdx.x & 31;
    float4 z = *reinterpret_cast<const float4*>(&g_z1[((size_t)(r * NN + n)) * F1 + lane * 4]);
    float4 a4 = *reinterpret_cast<const float4*>(&al[r * F1 + lane * 4]);
    float4 r4 = *reinterpret_cast<const float4*>(&ar[r * F1 + lane * 4]);
    float pl = z.x * a4.x + z.y * a4.y + z.z * a4.z + z.w * a4.w;
    float pr = z.x * r4.x + z.y * r4.y + z.z * r4.z + z.w * r4.w;
#pragma unroll
    for (int o = 4; o > 0; o >>= 1) {   // reduce within 8-lane head group
        pl += __shfl_xor_sync(0xffffffffu, pl, o);
        pr += __shfl_xor_sync(0xffffffffu, pr, o);
    }
    if ((lane & 7) == 0) {
        int h = lane >> 3;
        g_el1[(r * NN + n) * 4 + h] = pl;
        g_er1[(r * NN + n) * 4 + h] = pr;
    }
}

__global__ void k_attn2(const float* __restrict__ al, const float* __restrict__ ar) {
    int gw = (blockIdx.x * blockDim.x + threadIdx.x) >> 5;
    if (gw >= NN * RR) return;
    int r = gw / NN, n = gw - r * NN;
    int lane = threadIdx.x & 31;
    const float* zp = &g_z2[((size_t)(r * NN + n)) * F2 + lane * 8];
    const float* ap = &al[r * F2 + lane * 8];
    const float* rp = &ar[r * F2 + lane * 8];
    float4 z0 = *reinterpret_cast<const float4*>(zp);
    float4 z1 = *reinterpret_cast<const float4*>(zp + 4);
    float4 a0 = *reinterpret_cast<const float4*>(ap);
    float4 a1 = *reinterpret_cast<const float4*>(ap + 4);
    float4 r0 = *reinterpret_cast<const float4*>(rp);
    float4 r1 = *reinterpret_cast<const float4*>(rp + 4);
    float pl = z0.x * a0.x + z0.y * a0.y + z0.z * a0.z + z0.w * a0.w
             + z1.x * a1.x + z1.y * a1.y + z1.z * a1.z + z1.w * a1.w;
    float pr = z0.x * r0.x + z0.y * r0.y + z0.z * r0.z + z0.w * r0.w
             + z1.x * r1.x + z1.y * r1.y + z1.z * r1.z + z1.w * r1.w;
#pragma unroll
    for (int o = 4; o > 0; o >>= 1) {
        pl += __shfl_xor_sync(0xffffffffu, pl, o);
        pr += __shfl_xor_sync(0xffffffffu, pr, o);
    }
    if ((lane & 7) == 0) {
        int h = lane >> 3;
        g_el2[(r * NN + n) * 4 + h] = pl;
        g_er2[(r * NN + n) * 4 + h] = pr;
    }
}

// ---------------- layer-1 edge softmax + aggregation (warp per dst node) -----
__global__ void k_agg1(const float* __restrict__ b1) {
    int w = (blockIdx.x * blockDim.x + threadIdx.x) >> 5;
    int lane = threadIdx.x & 31;
    if (w >= NN) return;
    int n = w;
    float t0 = 0.f, t1 = 0.f, t2 = 0.f, t3 = 0.f;
#pragma unroll
    for (int r = 0; r < RR; r++) {
        int beg = g_rowoff[r * (NN + 1) + n];
        int end = g_rowoff[r * (NN + 1) + n + 1];
        if (beg == end) continue;
        const float4 erd = *reinterpret_cast<const float4*>(&g_er1[(r * NN + n) * 4]);
        float d0 = 0, d1 = 0, d2 = 0, d3 = 0, a0 = 0, a1 = 0, a2 = 0, a3 = 0;
        for (int i = beg; i < end; i++) {
            int s = g_col[(size_t)r * EE + i];
            float4 el = *reinterpret_cast<const float4*>(&g_el1[(r * NN + s) * 4]);
            float w0 = __expf(lrelu(el.x + erd.x));
            float w1 = __expf(lrelu(el.y + erd.y));
            float w2 = __expf(lrelu(el.z + erd.z));
            float w3 = __expf(lrelu(el.w + erd.w));
            d0 += w0; d1 += w1; d2 += w2; d3 += w3;
            const float* z = &g_z1[((size_t)(r * NN + s)) * F1];
            a0 += w0 * z[lane];
            a1 += w1 * z[32 + lane];
            a2 += w2 * z[64 + lane];
            a3 += w3 * z[96 + lane];
        }
        t0 += a0 / d0; t1 += a1 / d1; t2 += a2 / d2; t3 += a3 / d3;
    }
    t0 += b1[lane]      + b1[F1 + lane]      + b1[2 * F1 + lane];
    t1 += b1[32 + lane] + b1[F1 + 32 + lane] + b1[2 * F1 + 32 + lane];
    t2 += b1[64 + lane] + b1[F1 + 64 + lane] + b1[2 * F1 + 64 + lane];
    t3 += b1[96 + lane] + b1[F1 + 96 + lane] + b1[2 * F1 + 96 + lane];
    size_t o = (size_t)n * F1;
    g_h[o + lane]      = fmaxf(t0, 0.f);
    g_h[o + 32 + lane] = fmaxf(t1, 0.f);
    g_h[o + 64 + lane] = fmaxf(t2, 0.f);
    g_h[o + 96 + lane] = fmaxf(t3, 0.f);
}

// ---------------- layer-2 edge softmax + aggregation + head mean -------------
__global__ void k_agg2(const float* __restrict__ b2, float* __restrict__ out) {
    int w = (blockIdx.x * blockDim.x + threadIdx.x) >> 5;
    int lane = threadIdx.x & 31;
    if (w >= NN) return;
    int n = w;
    float t00 = 0, t01 = 0, t10 = 0, t11 = 0, t20 = 0, t21 = 0, t30 = 0, t31 = 0;
#pragma unroll
    for (int r = 0; r < RR; r++) {
        int beg = g_rowoff[r * (NN + 1) + n];
        int end = g_rowoff[r * (NN + 1) + n + 1];
        if (beg == end) continue;
        const float4 erd = *reinterpret_cast<const float4*>(&g_er2[(r * NN + n) * 4]);
        float d0 = 0, d1 = 0, d2 = 0, d3 = 0;
        float a00 = 0, a01 = 0, a10 = 0, a11 = 0, a20 = 0, a21 = 0, a30 = 0, a31 = 0;
        for (int i = beg; i < end; i++) {
            int s = g_col[(size_t)r * EE + i];
            float4 el = *reinterpret_cast<const float4*>(&g_el2[(r * NN + s) * 4]);
            float w0 = __expf(lrelu(el.x + erd.x));
            float w1 = __expf(lrelu(el.y + erd.y));
            float w2 = __expf(lrelu(el.z + erd.z));
            float w3 = __expf(lrelu(el.w + erd.w));
            d0 += w0; d1 += w1; d2 += w2; d3 += w3;
            const float* z = &g_z2[((size_t)(r * NN + s)) * F2];
            a00 += w0 * z[lane];        a01 += w0 * z[32 + lane];
            a10 += w1 * z[64 + lane];   a11 += w1 * z[96 + lane];
            a20 += w2 * z[128 + lane];  a21 += w2 * z[160 + lane];
            a30 += w3 * z[192 + lane];  a31 += w3 * z[224 + lane];
        }
        t00 += a00 / d0; t01 += a01 / d0;
        t10 += a10 / d1; t11 += a11 / d1;
        t20 += a20 / d2; t21 += a21 / d2;
        t30 += a30 / d3; t31 += a31 / d3;
    }
    t00 += b2[lane]       + b2[F2 + lane]       + b2[2 * F2 + lane];
    t01 += b2[32 + lane]  + b2[F2 + 32 + lane]  + b2[2 * F2 + 32 + lane];
    t10 += b2[64 + lane]  + b2[F2 + 64 + lane]  + b2[2 * F2 + 64 + lane];
    t11 += b2[96 + lane]  + b2[F2 + 96 + lane]  + b2[2 * F2 + 96 + lane];
    t20 += b2[128 + lane] + b2[F2 + 128 + lane] + b2[2 * F2 + 128 + lane];
    t21 += b2[160 + lane] + b2[F2 + 160 + lane] + b2[2 * F2 + 160 + lane];
    t30 += b2[192 + lane] + b2[F2 + 192 + lane] + b2[2 * F2 + 192 + lane];
    t31 += b2[224 + lane] + b2[F2 + 224 + lane] + b2[2 * F2 + 224 + lane];
    out[(size_t)n * 64 + lane]      = 0.25f * (t00 + t10 + t20 + t30);
    out[(size_t)n * 64 + 32 + lane] = 0.25f * (t01 + t11 + t21 + t31);
}

// ---------------- launch (single stream, round-4 topology) -------------------
extern "C" void kernel_launch(void* const* d_in, const int* in_sizes, int n_in,
                              void* d_out, int out_size) {
    const float* x   = (const float*)d_in[0];
    const int*   src = (const int*)d_in[1];
    const int*   dst = (const int*)d_in[2];
    const float* W1  = (const float*)d_in[3];
    const float* al1 = (const float*)d_in[4];
    const float* ar1 = (const float*)d_in[5];
    const float* b1  = (const float*)d_in[6];
    const float* W2  = (const float*)d_in[7];
    const float* al2 = (const float*)d_in[8];
    const float* ar2 = (const float*)d_in[9];
    const float* b2  = (const float*)d_in[10];
    float* out = (float*)d_out;

    // CSR by dst, per relation
    k_zero<<<(RR * NN + 255) / 256, 256>>>();
    k_hist<<<(RR * EE + 255) / 256, 256>>>(dst);
    k_scan<<<RR, 1024>>>();
    k_scatter<<<(RR * EE + 255) / 256, 256>>>(src, dst);

    // layer 1
    dim3 g1(F1 / 128, (NN + 127) / 128, RR);
    k_sgemm_tf32<<<g1, 256>>>(x, W1, NN, KIN, F1, 1);
    k_attn1<<<(NN * RR + 7) / 8, 256>>>(al1, ar1);
    k_agg1<<<(NN + 3) / 4, 128>>>(b1);

    // layer 2
    dim3 g2(F2 / 128, (NN + 127) / 128, RR);
    k_sgemm_tf32<<<g2, 256>>>(nullptr, W2, NN, F1, F2, 2);
    k_attn2<<<(NN * RR + 7) / 8, 256>>>(al2, ar2);
    k_agg2<<<(NN + 3) / 4, 128>>>(b2, out);
}

// round 10
// speedup vs baseline: 1.7198x; 1.0757x over previous
#include <cuda_runtime.h>
#include <cuda_fp16.h>
#include <math.h>

#define NN 30000
#define EE 300000
#define RR 3
#define KIN 256
#define F1 128   // HEADS*HID
#define F2 256   // HEADS*OUT

// ---------------- scratch (device globals; no allocation allowed) ----------
__device__ __align__(16) float  g_z1[(size_t)RR * NN * F1];    // 46 MB fp32
__device__ __align__(16) __half g_z2h[(size_t)RR * NN * F2];   // 46 MB fp16
__device__ __align__(16) float  g_h[(size_t)NN * F1];          // 15 MB
__device__ __align__(16) float g_el1[RR * NN * 4];
__device__ __align__(16) float g_er1[RR * NN * 4];
__device__ __align__(16) float g_el2[RR * NN * 4];
__device__ __align__(16) float g_er2[RR * NN * 4];
__device__ int g_deg[RR * NN];
__device__ int g_cur[RR * NN];
__device__ int g_rowoff[RR * (NN + 1)];
__device__ int g_col[RR * EE];

__device__ __forceinline__ float lrelu(float x) { return x > 0.f ? x : 0.2f * x; }

__device__ __forceinline__ unsigned f2tf32(float v) {
    unsigned u;
    asm("cvt.rna.tf32.f32 %0, %1;" : "=r"(u) : "f"(v));
    return u;
}

// ---------------- CSR build --------------------------------------------------
__global__ void k_zero() {
    int i = blockIdx.x * blockDim.x + threadIdx.x;
    if (i < RR * NN) { g_deg[i] = 0; g_cur[i] = 0; }
}

__global__ void k_hist(const int* __restrict__ dst) {
    int i = blockIdx.x * blockDim.x + threadIdx.x;
    if (i < RR * EE) {
        int r = i / EE;
        atomicAdd(&g_deg[r * NN + dst[i]], 1);
    }
}

__global__ void k_scan() {
    int r = blockIdx.x;
    __shared__ int sh[1024];
    __shared__ int carry;
    int t = threadIdx.x;
    if (t == 0) { carry = 0; g_rowoff[r * (NN + 1)] = 0; }
    __syncthreads();
    for (int base = 0; base < NN; base += 1024) {
        int i = base + t;
        int v = (i < NN) ? g_deg[r * NN + i] : 0;
        sh[t] = v;
        __syncthreads();
        for (int off = 1; off < 1024; off <<= 1) {
            int x = (t >= off) ? sh[t - off] : 0;
            __syncthreads();
            sh[t] += x;
            __syncthreads();
        }
        if (i < NN) g_rowoff[r * (NN + 1) + i + 1] = carry + sh[t];
        __syncthreads();
        if (t == 0) carry += sh[1023];
        __syncthreads();
    }
}

__global__ void k_scatter(const int* __restrict__ src, const int* __restrict__ dst) {
    int i = blockIdx.x * blockDim.x + threadIdx.x;
    if (i < RR * EE) {
        int r = i / EE;
        int d = dst[i];
        int pos = atomicAdd(&g_cur[r * NN + d], 1);
        g_col[(size_t)r * EE + g_rowoff[r * (NN + 1) + d] + pos] = src[i];
    }
}

// ---------------- TF32 tensor-core GEMM: C[r] = A @ B[r] ---------------------
// layer 1: C = g_z1 (fp32); layer 2: C = g_z2h (fp16)
#define SSTR 132

__global__ __launch_bounds__(256, 2)
void k_sgemm_tf32(const float* __restrict__ Aext, const float* __restrict__ Bg,
                  int M, int K, int Nc, int layer) {
    const float* A = (layer == 1) ? Aext : g_h;
    int r = blockIdx.z;
    const float* B = Bg + (size_t)r * K * Nc;

    __shared__ unsigned As[2][16 * SSTR];   // [k][m]
    __shared__ unsigned Bs[2][16 * SSTR];   // [k][n]

    int tid = threadIdx.x;
    int lane = tid & 31;
    int wid = tid >> 5;
    int wm = (wid & 1) * 64;
    int wn = (wid >> 1) * 32;
    int gid = lane >> 2;
    int tig = lane & 3;

    int row0 = blockIdx.y * 128, col0 = blockIdx.x * 128;

    int am = tid >> 2;
    int ak = (tid & 3) * 4;
    int bk = tid >> 4;
    int bn = (tid & 15) * 4;

    float acc[4][4][4];
#pragma unroll
    for (int i = 0; i < 4; i++)
#pragma unroll
        for (int j = 0; j < 4; j++)
#pragma unroll
            for (int q = 0; q < 4; q++) acc[i][j][q] = 0.f;

    int nstage = K >> 4;

    {
        float4 va0, va1, vb0, vb1;
        int gr0 = row0 + am, gr1 = row0 + am + 64;
        va0 = (gr0 < M) ? *reinterpret_cast<const float4*>(&A[(size_t)gr0 * K + ak])
                        : make_float4(0, 0, 0, 0);
        va1 = (gr1 < M) ? *reinterpret_cast<const float4*>(&A[(size_t)gr1 * K + ak])
                        : make_float4(0, 0, 0, 0);
        vb0 = *reinterpret_cast<const float4*>(&B[(size_t)bk * Nc + col0 + bn]);
        vb1 = *reinterpret_cast<const float4*>(&B[(size_t)bk * Nc + col0 + 64 + bn]);
        As[0][(ak + 0) * SSTR + am] = f2tf32(va0.x);
        As[0][(ak + 1) * SSTR + am] = f2tf32(va0.y);
        As[0][(ak + 2) * SSTR + am] = f2tf32(va0.z);
        As[0][(ak + 3) * SSTR + am] = f2tf32(va0.w);
        As[0][(ak + 0) * SSTR + am + 64] = f2tf32(va1.x);
        As[0][(ak + 1) * SSTR + am + 64] = f2tf32(va1.y);
        As[0][(ak + 2) * SSTR + am + 64] = f2tf32(va1.z);
        As[0][(ak + 3) * SSTR + am + 64] = f2tf32(va1.w);
        Bs[0][bk * SSTR + bn + 0] = f2tf32(vb0.x);
        Bs[0][bk * SSTR + bn + 1] = f2tf32(vb0.y);
        Bs[0][bk * SSTR + bn + 2] = f2tf32(vb0.z);
        Bs[0][bk * SSTR + bn + 3] = f2tf32(vb0.w);
        Bs[0][bk * SSTR + 64 + bn + 0] = f2tf32(vb1.x);
        Bs[0][bk * SSTR + 64 + bn + 1] = f2tf32(vb1.y);
        Bs[0][bk * SSTR + 64 + bn + 2] = f2tf32(vb1.z);
        Bs[0][bk * SSTR + 64 + bn + 3] = f2tf32(vb1.w);
    }
    __syncthreads();

    int buf = 0;
    for (int s = 0; s < nstage; s++) {
        float4 va0, va1, vb0, vb1;
        bool more = (s + 1) < nstage;
        if (more) {
            int k0 = (s + 1) << 4;
            int gr0 = row0 + am, gr1 = row0 + am + 64;
            va0 = (gr0 < M) ? *reinterpret_cast<const float4*>(&A[(size_t)gr0 * K + k0 + ak])
                            : make_float4(0, 0, 0, 0);
            va1 = (gr1 < M) ? *reinterpret_cast<const float4*>(&A[(size_t)gr1 * K + k0 + ak])
                            : make_float4(0, 0, 0, 0);
            vb0 = *reinterpret_cast<const float4*>(&B[(size_t)(k0 + bk) * Nc + col0 + bn]);
            vb1 = *reinterpret_cast<const float4*>(&B[(size_t)(k0 + bk) * Nc + col0 + 64 + bn]);
        }

        const unsigned* as = As[buf];
        const unsigned* bs = Bs[buf];
#pragma unroll
        for (int kk = 0; kk < 16; kk += 8) {
            unsigned a[4][4], b[4][2];
#pragma unroll
            for (int i = 0; i < 4; i++) {
                int m = wm + i * 16 + gid;
                a[i][0] = as[(kk + tig) * SSTR + m];
                a[i][1] = as[(kk + tig) * SSTR + m + 8];
                a[i][2] = as[(kk + tig + 4) * SSTR + m];
                a[i][3] = as[(kk + tig + 4) * SSTR + m + 8];
            }
#pragma unroll
            for (int j = 0; j < 4; j++) {
                int n = wn + j * 8 + gid;
                b[j][0] = bs[(kk + tig) * SSTR + n];
                b[j][1] = bs[(kk + tig + 4) * SSTR + n];
            }
#pragma unroll
            for (int i = 0; i < 4; i++)
#pragma unroll
                for (int j = 0; j < 4; j++) {
                    asm volatile(
                        "mma.sync.aligned.m16n8k8.row.col.f32.tf32.tf32.f32 "
                        "{%0,%1,%2,%3}, {%4,%5,%6,%7}, {%8,%9}, {%0,%1,%2,%3};\n"
                        : "+f"(acc[i][j][0]), "+f"(acc[i][j][1]),
                          "+f"(acc[i][j][2]), "+f"(acc[i][j][3])
                        : "r"(a[i][0]), "r"(a[i][1]), "r"(a[i][2]), "r"(a[i][3]),
                          "r"(b[j][0]), "r"(b[j][1]));
                }
        }

        if (more) {
            unsigned* asn = As[buf ^ 1];
            unsigned* bsn = Bs[buf ^ 1];
            asn[(ak + 0) * SSTR + am] = f2tf32(va0.x);
            asn[(ak + 1) * SSTR + am] = f2tf32(va0.y);
            asn[(ak + 2) * SSTR + am] = f2tf32(va0.z);
            asn[(ak + 3) * SSTR + am] = f2tf32(va0.w);
            asn[(ak + 0) * SSTR + am + 64] = f2tf32(va1.x);
            asn[(ak + 1) * SSTR + am + 64] = f2tf32(va1.y);
            asn[(ak + 2) * SSTR + am + 64] = f2tf32(va1.z);
            asn[(ak + 3) * SSTR + am + 64] = f2tf32(va1.w);
            bsn[bk * SSTR + bn + 0] = f2tf32(vb0.x);
            bsn[bk * SSTR + bn + 1] = f2tf32(vb0.y);
            bsn[bk * SSTR + bn + 2] = f2tf32(vb0.z);
            bsn[bk * SSTR + bn + 3] = f2tf32(vb0.w);
            bsn[bk * SSTR + 64 + bn + 0] = f2tf32(vb1.x);
            bsn[bk * SSTR + 64 + bn + 1] = f2tf32(vb1.y);
            bsn[bk * SSTR + 64 + bn + 2] = f2tf32(vb1.z);
            bsn[bk * SSTR + 64 + bn + 3] = f2tf32(vb1.w);
        }
        __syncthreads();
        buf ^= 1;
    }

    if (layer == 1) {
        float* C = g_z1 + (size_t)r * M * Nc;
#pragma unroll
        for (int i = 0; i < 4; i++)
#pragma unroll
            for (int j = 0; j < 4; j++) {
                int gr = row0 + wm + i * 16 + gid;
                int gc = col0 + wn + j * 8 + 2 * tig;
                if (gr < M)
                    *reinterpret_cast<float2*>(&C[(size_t)gr * Nc + gc]) =
                        make_float2(acc[i][j][0], acc[i][j][1]);
                if (gr + 8 < M)
                    *reinterpret_cast<float2*>(&C[(size_t)(gr + 8) * Nc + gc]) =
                        make_float2(acc[i][j][2], acc[i][j][3]);
            }
    } else {
        __half* C = g_z2h + (size_t)r * M * Nc;
#pragma unroll
        for (int i = 0; i < 4; i++)
#pragma unroll
            for (int j = 0; j < 4; j++) {
                int gr = row0 + wm + i * 16 + gid;
                int gc = col0 + wn + j * 8 + 2 * tig;
                if (gr < M)
                    *reinterpret_cast<__half2*>(&C[(size_t)gr * Nc + gc]) =
                        __floats2half2_rn(acc[i][j][0], acc[i][j][1]);
                if (gr + 8 < M)
                    *reinterpret_cast<__half2*>(&C[(size_t)(gr + 8) * Nc + gc]) =
                        __floats2half2_rn(acc[i][j][2], acc[i][j][3]);
            }
    }
}

// ---------------- attention projections: warp per (node, relation) -----------
__global__ void k_attn1(const float* __restrict__ al, const float* __restrict__ ar) {
    int gw = (blockIdx.x * blockDim.x + threadIdx.x) >> 5;
    if (gw >= NN * RR) return;
    int r = gw / NN, n = gw - r * NN;
    int lane = threadIdx.x & 31;
    float4 z = *reinterpret_cast<const float4*>(&g_z1[((size_t)(r * NN + n)) * F1 + lane * 4]);
    float4 a4 = *reinterpret_cast<const float4*>(&al[r * F1 + lane * 4]);
    float4 r4 = *reinterpret_cast<const float4*>(&ar[r * F1 + lane * 4]);
    float pl = z.x * a4.x + z.y * a4.y + z.z * a4.z + z.w * a4.w;
    float pr = z.x * r4.x + z.y * r4.y + z.z * r4.z + z.w * r4.w;
#pragma unroll
    for (int o = 4; o > 0; o >>= 1) {
        pl += __shfl_xor_sync(0xffffffffu, pl, o);
        pr += __shfl_xor_sync(0xffffffffu, pr, o);
    }
    if ((lane & 7) == 0) {
        int h = lane >> 3;
        g_el1[(r * NN + n) * 4 + h] = pl;
        g_er1[(r * NN + n) * 4 + h] = pr;
    }
}

// attn2 reads fp16 z2: lane handles 8 cols = one uint4 (8 halves)
__global__ void k_attn2(const float* __restrict__ al, const float* __restrict__ ar) {
    int gw = (blockIdx.x * blockDim.x + threadIdx.x) >> 5;
    if (gw >= NN * RR) return;
    int r = gw / NN, n = gw - r * NN;
    int lane = threadIdx.x & 31;
    const __half2* zp = reinterpret_cast<const __half2*>(
        &g_z2h[((size_t)(r * NN + n)) * F2 + lane * 8]);
    float z[8];
#pragma unroll
    for (int q = 0; q < 4; q++) {
        float2 f = __half22float2(zp[q]);
        z[2 * q] = f.x; z[2 * q + 1] = f.y;
    }
    const float* ap = &al[r * F2 + lane * 8];
    const float* rp = &ar[r * F2 + lane * 8];
    float4 a0 = *reinterpret_cast<const float4*>(ap);
    float4 a1 = *reinterpret_cast<const float4*>(ap + 4);
    float4 r0 = *reinterpret_cast<const float4*>(rp);
    float4 r1 = *reinterpret_cast<const float4*>(rp + 4);
    float pl = z[0] * a0.x + z[1] * a0.y + z[2] * a0.z + z[3] * a0.w
             + z[4] * a1.x + z[5] * a1.y + z[6] * a1.z + z[7] * a1.w;
    float pr = z[0] * r0.x + z[1] * r0.y + z[2] * r0.z + z[3] * r0.w
             + z[4] * r1.x + z[5] * r1.y + z[6] * r1.z + z[7] * r1.w;
#pragma unroll
    for (int o = 4; o > 0; o >>= 1) {
        pl += __shfl_xor_sync(0xffffffffu, pl, o);
        pr += __shfl_xor_sync(0xffffffffu, pr, o);
    }
    if ((lane & 7) == 0) {
        int h = lane >> 3;
        g_el2[(r * NN + n) * 4 + h] = pl;
        g_er2[(r * NN + n) * 4 + h] = pr;
    }
}

// ---------------- layer-1 edge softmax + aggregation (warp per dst node) -----
__global__ void k_agg1(const float* __restrict__ b1) {
    int w = (blockIdx.x * blockDim.x + threadIdx.x) >> 5;
    int lane = threadIdx.x & 31;
    if (w >= NN) return;
    int n = w;
    float t0 = 0.f, t1 = 0.f, t2 = 0.f, t3 = 0.f;
#pragma unroll
    for (int r = 0; r < RR; r++) {
        int beg = g_rowoff[r * (NN + 1) + n];
        int end = g_rowoff[r * (NN + 1) + n + 1];
        if (beg == end) continue;
        const float4 erd = *reinterpret_cast<const float4*>(&g_er1[(r * NN + n) * 4]);
        float d0 = 0, d1 = 0, d2 = 0, d3 = 0, a0 = 0, a1 = 0, a2 = 0, a3 = 0;
        for (int i = beg; i < end; i++) {
            int s = g_col[(size_t)r * EE + i];
            float4 el = *reinterpret_cast<const float4*>(&g_el1[(r * NN + s) * 4]);
            float w0 = __expf(lrelu(el.x + erd.x));
            float w1 = __expf(lrelu(el.y + erd.y));
            float w2 = __expf(lrelu(el.z + erd.z));
            float w3 = __expf(lrelu(el.w + erd.w));
            d0 += w0; d1 += w1; d2 += w2; d3 += w3;
            const float* z = &g_z1[((size_t)(r * NN + s)) * F1];
            a0 += w0 * z[lane];
            a1 += w1 * z[32 + lane];
            a2 += w2 * z[64 + lane];
            a3 += w3 * z[96 + lane];
        }
        t0 += a0 / d0; t1 += a1 / d1; t2 += a2 / d2; t3 += a3 / d3;
    }
    t0 += b1[lane]      + b1[F1 + lane]      + b1[2 * F1 + lane];
    t1 += b1[32 + lane] + b1[F1 + 32 + lane] + b1[2 * F1 + 32 + lane];
    t2 += b1[64 + lane] + b1[F1 + 64 + lane] + b1[2 * F1 + 64 + lane];
    t3 += b1[96 + lane] + b1[F1 + 96 + lane] + b1[2 * F1 + 96 + lane];
    size_t o = (size_t)n * F1;
    g_h[o + lane]      = fmaxf(t0, 0.f);
    g_h[o + 32 + lane] = fmaxf(t1, 0.f);
    g_h[o + 64 + lane] = fmaxf(t2, 0.f);
    g_h[o + 96 + lane] = fmaxf(t3, 0.f);
}

// ------- layer-2 agg (fp16 z2): lane owns out cols {2*lane, 2*lane+1} --------
__global__ void k_agg2(const float* __restrict__ b2, float* __restrict__ out) {
    int w = (blockIdx.x * blockDim.x + threadIdx.x) >> 5;
    int lane = threadIdx.x & 31;
    if (w >= NN) return;
    int n = w;
    // t[h][0..1]: aggregated cols {2*lane, 2*lane+1} of head h
    float t00 = 0, t01 = 0, t10 = 0, t11 = 0, t20 = 0, t21 = 0, t30 = 0, t31 = 0;
#pragma unroll
    for (int r = 0; r < RR; r++) {
        int beg = g_rowoff[r * (NN + 1) + n];
        int end = g_rowoff[r * (NN + 1) + n + 1];
        if (beg == end) continue;
        const float4 erd = *reinterpret_cast<const float4*>(&g_er2[(r * NN + n) * 4]);
        float d0 = 0, d1 = 0, d2 = 0, d3 = 0;
        float a00 = 0, a01 = 0, a10 = 0, a11 = 0, a20 = 0, a21 = 0, a30 = 0, a31 = 0;
        for (int i = beg; i < end; i++) {
            int s = g_col[(size_t)r * EE + i];
            float4 el = *reinterpret_cast<const float4*>(&g_el2[(r * NN + s) * 4]);
            float w0 = __expf(lrelu(el.x + erd.x));
            float w1 = __expf(lrelu(el.y + erd.y));
            float w2 = __expf(lrelu(el.z + erd.z));
            float w3 = __expf(lrelu(el.w + erd.w));
            d0 += w0; d1 += w1; d2 += w2; d3 += w3;
            const __half2* z = reinterpret_cast<const __half2*>(
                &g_z2h[((size_t)(r * NN + s)) * F2]);
            float2 f0 = __half22float2(z[lane]);          // head 0: cols 2*lane..+1
            float2 f1 = __half22float2(z[32 + lane]);     // head 1
            float2 f2 = __half22float2(z[64 + lane]);     // head 2
            float2 f3 = __half22float2(z[96 + lane]);     // head 3
            a00 += w0 * f0.x; a01 += w0 * f0.y;
            a10 += w1 * f1.x; a11 += w1 * f1.y;
            a20 += w2 * f2.x; a21 += w2 * f2.y;
            a30 += w3 * f3.x; a31 += w3 * f3.y;
        }
        t00 += a00 / d0; t01 += a01 / d0;
        t10 += a10 / d1; t11 += a11 / d1;
        t20 += a20 / d2; t21 += a21 / d2;
        t30 += a30 / d3; t31 += a31 / d3;
    }
    // biases: head h, cols 2*lane and 2*lane+1, summed over relations
    int c0 = 2 * lane, c1 = 2 * lane + 1;
    t00 += b2[c0]       + b2[F2 + c0]       + b2[2 * F2 + c0];
    t01 += b2[c1]       + b2[F2 + c1]       + b2[2 * F2 + c1];
    t10 += b2[64 + c0]  + b2[F2 + 64 + c0]  + b2[2 * F2 + 64 + c0];
    t11 += b2[64 + c1]  + b2[F2 + 64 + c1]  + b2[2 * F2 + 64 + c1];
    t20 += b2[128 + c0] + b2[F2 + 128 + c0] + b2[2 * F2 + 128 + c0];
    t21 += b2[128 + c1] + b2[F2 + 128 + c1] + b2[2 * F2 + 128 + c1];
    t30 += b2[192 + c0] + b2[F2 + 192 + c0] + b2[2 * F2 + 192 + c0];
    t31 += b2[192 + c1] + b2[F2 + 192 + c1] + b2[2 * F2 + 192 + c1];
    *reinterpret_cast<float2*>(&out[(size_t)n * 64 + c0]) =
        make_float2(0.25f * (t00 + t10 + t20 + t30),
                    0.25f * (t01 + t11 + t21 + t31));
}

// ---------------- launch (single stream) -------------------------------------
extern "C" void kernel_launch(void* const* d_in, const int* in_sizes, int n_in,
                              void* d_out, int out_size) {
    const float* x   = (const float*)d_in[0];
    const int*   src = (const int*)d_in[1];
    const int*   dst = (const int*)d_in[2];
    const float* W1  = (const float*)d_in[3];
    const float* al1 = (const float*)d_in[4];
    const float* ar1 = (const float*)d_in[5];
    const float* b1  = (const float*)d_in[6];
    const float* W2  = (const float*)d_in[7];
    const float* al2 = (const float*)d_in[8];
    const float* ar2 = (const float*)d_in[9];
    const float* b2  = (const float*)d_in[10];
    float* out = (float*)d_out;

    // CSR by dst, per relation
    k_zero<<<(RR * NN + 255) / 256, 256>>>();
    k_hist<<<(RR * EE + 255) / 256, 256>>>(dst);
    k_scan<<<RR, 1024>>>();
    k_scatter<<<(RR * EE + 255) / 256, 256>>>(src, dst);

    // layer 1
    dim3 g1(F1 / 128, (NN + 127) / 128, RR);
    k_sgemm_tf32<<<g1, 256>>>(x, W1, NN, KIN, F1, 1);
    k_attn1<<<(NN * RR + 7) / 8, 256>>>(al1, ar1);
    k_agg1<<<(NN + 3) / 4, 128>>>(b1);

    // layer 2
    dim3 g2(F2 / 128, (NN + 127) / 128, RR);
    k_sgemm_tf32<<<g2, 256>>>(nullptr, W2, NN, F1, F2, 2);
    k_attn2<<<(NN * RR + 7) / 8, 256>>>(al2, ar2);
    k_agg2<<<(NN + 3) / 4, 128>>>(b2, out);
}